// round 12
// baseline (speedup 1.0000x reference)
#include <cuda_runtime.h>
#include <cfloat>
#include <math.h>

#define FULL 0xffffffffu

constexpr int B = 4;
constexpr int N = 8192;
constexpr int M = 4096;
constexpr int F = 64;
constexpr int K = 16;
constexpr float MIN_SIGMA = 1e-4f;

constexpr int   NBX   = 128;      // x-bins
constexpr int   NYB   = 32;       // y-sub-bins per x-bin (width 0.2)
constexpr int   NBINS = NBX * NYB;
constexpr float XLO   = -3.2f;
constexpr float XW    = 0.05f;
constexpr float XINVW = 20.0f;
constexpr float YLO   = -3.2f;
constexpr float YINVW = 5.0f;
constexpr float EPSP  = 1e-4f;    // conservative pad (x gaps / y windows)
constexpr int   P1HALF = 3;       // pass-1 home y-window: +-3 sub-bins (+-0.6)
constexpr int   NWARPS = 37 * 32; // warps per batch

// Scratch (no allocations allowed)
__device__ float  g_featT[(size_t)B * N * F];    // (B,N,F) transposed features
__device__ float4 g_sorted[B * N];               // points, (xb,yb)-sorted
__device__ float4 g_qsorted[B * M];              // queries, (xb,yb)-sorted
__device__ int    g_start[B * (NBINS + 1)];      // point bin offsets
__device__ int    g_task[B];                     // dynamic task counters

// ---------------------------------------------------------------------------
__device__ __forceinline__ int xbinf(float x) {
    return min(NBX - 1, max(0, (int)floorf((x - XLO) * XINVW)));
}
__device__ __forceinline__ int ybinf(float y) {
    return min(NYB - 1, max(0, (int)floorf((y - YLO) * YINVW)));
}
__device__ __forceinline__ int bin2(float x, float y) {
    return xbinf(x) * NYB + ybinf(y);
}

// ---------------------------------------------------------------------------
// Fused build + transpose in ONE launch.
// Blocks 0..7: per-(kind,batch) binning (smem histogram + scan + scatter).
// Blocks 8..263: feature transpose, 8 32x32 tiles each (runs concurrently).
// ---------------------------------------------------------------------------
__global__ void __launch_bounds__(1024, 1)
build_kernel(const float* __restrict__ pc, const float* __restrict__ qc,
             const float* __restrict__ feat) {
    __shared__ int cnt[NBINS];
    __shared__ int cur[NBINS];
    __shared__ int wsum[32];
    __shared__ float tile[32][33];
    const int g = blockIdx.x;
    const int tid = threadIdx.x;

    if (g >= 2 * B) {
        // ---- transpose role: 8 tiles of 32x32, one element per thread ----
        const int tx = tid & 31, ty = tid >> 5;
        const int base_t = (g - 2 * B) * 8;
        #pragma unroll
        for (int it = 0; it < 8; it++) {
            const int tIdx = base_t + it;
            const int b   = tIdx >> 9;            // 512 tiles per batch
            const int rem = tIdx & 511;
            const int f0  = (rem >> 8) << 5;      // F/32 = 2
            const int n0  = (rem & 255) << 5;     // N/32 = 256
            __syncthreads();
            tile[ty][tx] = feat[((size_t)b * F + (f0 + ty)) * N + (n0 + tx)];
            __syncthreads();
            g_featT[((size_t)b * N + (n0 + ty)) * F + (f0 + tx)] = tile[tx][ty];
        }
        return;
    }

    // ---- binning role ----
    const bool isQ = g >= B;
    const int b = isQ ? g - B : g;
    const int n = isQ ? M : N;
    const float* src = isQ ? qc + (size_t)b * 3 * M : pc + (size_t)b * 3 * N;
    float4* dst = isQ ? g_qsorted + (size_t)b * M : g_sorted + (size_t)b * N;
    const int lane = tid & 31, wid = tid >> 5;

    if (g == 0 && tid < B) g_task[tid] = NWARPS;   // first NWARPS tasks static

    for (int i = tid; i < NBINS; i += 1024) cnt[i] = 0;
    __syncthreads();
    for (int i = tid; i < n; i += 1024)
        atomicAdd(&cnt[bin2(src[i], src[n + i])], 1);
    __syncthreads();

    // block exclusive scan, 4 bins per thread
    const int o = tid * 4;
    const int v0 = cnt[o], v1 = cnt[o + 1], v2 = cnt[o + 2], v3 = cnt[o + 3];
    const int tsum = v0 + v1 + v2 + v3;
    int inc = tsum;
    #pragma unroll
    for (int off = 1; off < 32; off <<= 1) {
        int nb = __shfl_up_sync(FULL, inc, off);
        if (lane >= off) inc += nb;
    }
    if (lane == 31) wsum[wid] = inc;
    __syncthreads();
    if (wid == 0) {
        int v = wsum[lane];
        #pragma unroll
        for (int off = 1; off < 32; off <<= 1) {
            int nb = __shfl_up_sync(FULL, v, off);
            if (lane >= off) v += nb;
        }
        wsum[lane] = v;
    }
    __syncthreads();
    int acc = (wid ? wsum[wid - 1] : 0) + inc - tsum;
    const int sb = b * (NBINS + 1);
    cur[o] = acc;
    if (!isQ) g_start[sb + o] = acc;
    acc += v0;
    cur[o + 1] = acc;
    if (!isQ) g_start[sb + o + 1] = acc;
    acc += v1;
    cur[o + 2] = acc;
    if (!isQ) g_start[sb + o + 2] = acc;
    acc += v2;
    cur[o + 3] = acc;
    if (!isQ) g_start[sb + o + 3] = acc;
    acc += v3;
    if (!isQ && tid == 1023) g_start[sb + NBINS] = acc;
    __syncthreads();
    for (int i = tid; i < n; i += 1024) {
        const float x = src[i], y = src[n + i], z = src[2 * n + i];
        const int pos = atomicAdd(&cur[bin2(x, y)], 1);
        dst[pos] = make_float4(x, y, z, __int_as_float(i));
    }
}

// ---------------------------------------------------------------------------
// Streamlined warp-cooperative top-K insert (non-improving candidates are
// natural no-ops). Caller refreshes the warp-uniform threshold per chunk.
// ---------------------------------------------------------------------------
__device__ __forceinline__ void topk_insert(float s, int pidx, int lane,
                                            float& val, int& idx,
                                            float threshold, int base) {
    unsigned bal = __ballot_sync(FULL, s < threshold);
    const bool mine = (unsigned)(lane - base) < (unsigned)K;
    while (bal) {
        const int src = __ffs(bal) - 1;
        bal &= bal - 1;
        const float cs = __shfl_sync(FULL, s, src);
        const int   ci = __shfl_sync(FULL, pidx, src);
        const unsigned less = __ballot_sync(FULL, mine && (val <= cs));
        const int pos = base + __popc(less);
        const float ot = __shfl_up_sync(FULL, val, 1);
        const int   oi = __shfl_up_sync(FULL, idx, 1);
        if (mine) {
            if (lane == pos)     { val = cs; idx = ci; }
            else if (lane > pos) { val = ot; idx = oi; }
        }
    }
}

// ---------------------------------------------------------------------------
// Query kernel: one warp, TWO (x,y)-adjacent queries per task.
// Home x-bin scanned first over a CENTERED +-0.6 y-window (lazy bitonic
// init) -> th ~ true d16 immediately; pass-2 patches the th-window; x
// expansion L/R with one contiguous th-derived y-window per bin.
// ---------------------------------------------------------------------------
__global__ void __launch_bounds__(1024, 1)
soft_projection_query(const float* __restrict__ temp,
                      float* __restrict__ out) {
    extern __shared__ char smraw[];
    float4* spts = (float4*)smraw;                                    // 128KB
    int*   cst = (int*)(smraw + 131072);                              // 4097 ints
    float* stw = (float*)(smraw + 131072 + 16392);                    // 4KB
    int*   sti = (int*)  (smraw + 131072 + 16392 + 4096);             // 4KB

    const int b = blockIdx.y;
    for (int i = threadIdx.x; i < N; i += blockDim.x) spts[i] = g_sorted[b * N + i];
    for (int i = threadIdx.x; i < NBINS + 1; i += blockDim.x)
        cst[i] = g_start[b * (NBINS + 1) + i];
    __syncthreads();

    const float t = *temp;
    const float inv_sigma = 1.0f / fmaxf(t * t, MIN_SIGMA);

    const int lane = threadIdx.x & 31;
    const int warp = threadIdx.x >> 5;
    float* mysw = stw + warp * 32;
    int*   mysi = sti + warp * 32;

    float* out_pts  = out + (size_t)b * 3 * M;
    float* out_feat = out + (size_t)B * 3 * M + (size_t)b * F * M;
    const float* featb = g_featT + (size_t)b * N * F;
    const float4* qs = g_qsorted + (size_t)b * M;

    constexpr int NT = M / 2;           // 2048 tasks per batch
    const int wg = blockIdx.x * 32 + warp;

    for (int pos = wg; pos < NT; ) {
        // center-out (x) order: longest tasks first
        const int task = (NT / 2) + ((pos & 1) ? -((pos + 1) >> 1) : (pos >> 1));

        const float4 QA = qs[2 * task];
        const float4 QB = qs[2 * task + 1];
        const int mA = __float_as_int(QA.w);
        const int mB = __float_as_int(QB.w);

        float val = FLT_MAX, thA = FLT_MAX, thB = FLT_MAX;
        int   idx = 0;
        bool  init = false;

        // scan [s,e): first 32 points bitonic-init the lists, then chunks
        auto scan_raw = [&](int s, int e) {
            if (s >= e) return;
            if (!init) {
                const int p = s + lane;
                float dA = FLT_MAX, dB = FLT_MAX;
                int pA = p, pB = p;
                if (p < e) {
                    const float4 pt = spts[p];
                    const float aX = pt.x - QA.x, aY = pt.y - QA.y, aZ = pt.z - QA.z;
                    const float bX = pt.x - QB.x, bY = pt.y - QB.y, bZ = pt.z - QB.z;
                    dA = fmaf(aX, aX, fmaf(aY, aY, aZ * aZ));
                    dB = fmaf(bX, bX, fmaf(bY, bY, bZ * bZ));
                }
                #pragma unroll
                for (int k = 2; k <= 32; k <<= 1) {
                    #pragma unroll
                    for (int j = k >> 1; j > 0; j >>= 1) {
                        const float ovA = __shfl_xor_sync(FULL, dA, j);
                        const int   oiA = __shfl_xor_sync(FULL, pA, j);
                        const float ovB = __shfl_xor_sync(FULL, dB, j);
                        const int   oiB = __shfl_xor_sync(FULL, pB, j);
                        const bool ks = ((lane & j) == 0) == ((lane & k) == 0);
                        if (ks ? (ovA < dA) : (ovA > dA)) { dA = ovA; pA = oiA; }
                        if (ks ? (ovB < dB) : (ovB > dB)) { dB = ovB; pB = oiB; }
                    }
                }
                const float dBs = __shfl_sync(FULL, dB, lane - 16);
                const int   pBs = __shfl_sync(FULL, pB, lane - 16);
                val = (lane < 16) ? dA : dBs;
                idx = (lane < 16) ? pA : pBs;
                thA = __shfl_sync(FULL, val, K - 1);
                thB = __shfl_sync(FULL, val, 16 + K - 1);
                init = true;
                s = min(s + 32, e);
            }
            for (int p0 = s; p0 < e; p0 += 64) {
                const int q0 = p0 + lane, q1 = p0 + lane + 32;
                float dA0 = FLT_MAX, dA1 = FLT_MAX, dB0 = FLT_MAX, dB1 = FLT_MAX;
                if (q0 < e) {
                    const float4 pt = spts[q0];
                    const float aX = pt.x - QA.x, aY = pt.y - QA.y, aZ = pt.z - QA.z;
                    const float bX = pt.x - QB.x, bY = pt.y - QB.y, bZ = pt.z - QB.z;
                    dA0 = fmaf(aX, aX, fmaf(aY, aY, aZ * aZ));
                    dB0 = fmaf(bX, bX, fmaf(bY, bY, bZ * bZ));
                }
                if (q1 < e) {
                    const float4 pt = spts[q1];
                    const float aX = pt.x - QA.x, aY = pt.y - QA.y, aZ = pt.z - QA.z;
                    const float bX = pt.x - QB.x, bY = pt.y - QB.y, bZ = pt.z - QB.z;
                    dA1 = fmaf(aX, aX, fmaf(aY, aY, aZ * aZ));
                    dB1 = fmaf(bX, bX, fmaf(bY, bY, bZ * bZ));
                }
                const bool cc = (fminf(dA0, dA1) < thA) | (fminf(dB0, dB1) < thB);
                if (__any_sync(FULL, cc)) {
                    topk_insert(dA0, q0, lane, val, idx, thA, 0);
                    topk_insert(dA1, q1, lane, val, idx, thA, 0);
                    topk_insert(dB0, q0, lane, val, idx, thB, 16);
                    topk_insert(dB1, q1, lane, val, idx, thB, 16);
                    thA = __shfl_sync(FULL, val, K - 1);
                    thB = __shfl_sync(FULL, val, 16 + K - 1);
                }
            }
        };

        // y-window [lo,hi] from radius ry around the pair's y extent
        const float ymn = fminf(QA.y, QB.y), ymx = fmaxf(QA.y, QB.y);
        auto ywin = [&](float ry, int& lo, int& hi) {
            lo = max(0, min(NYB - 1, (int)floorf((ymn - ry - YLO) * YINVW)));
            hi = max(0, min(NYB - 1, (int)floorf((ymx + ry - YLO) * YINVW)));
        };

        const int h   = xbinf(0.5f * (QA.x + QB.x));
        const int ybq = ybinf(0.5f * (QA.y + QB.y));

        // ---- home bin pass 1: centered +-P1HALF sub-bin y-window ----
        const int p1lo = max(0, ybq - P1HALF);
        const int p1hi = min(NYB - 1, ybq + P1HALF);
        scan_raw(cst[h * NYB + p1lo], cst[h * NYB + p1hi + 1]);

        // ---- home bin pass 2: patch the full th-derived window ----
        {
            const float ry = sqrtf(fmaxf(thA, thB)) + EPSP;
            int lo, hi;
            ywin(ry, lo, hi);
            if (lo < p1lo) scan_raw(cst[h * NYB + lo], cst[h * NYB + p1lo]);
            if (hi > p1hi) scan_raw(cst[h * NYB + p1hi + 1], cst[h * NYB + hi + 1]);
        }

        // one contiguous y-window scan of x-bin bx
        auto process_bin = [&](int bx, float gA2, float gB2) {
            const float avail = fmaxf(thA - gA2, thB - gB2);
            if (avail <= 0.0f) return;
            const float ry = sqrtf(avail) + EPSP;
            int lo, hi;
            ywin(ry, lo, hi);
            scan_raw(cst[bx * NYB + lo], cst[bx * NYB + hi + 1]);
        };

        for (int l = h - 1; l >= 0; l--) {           // left expansion
            const float edge = XLO + (l + 1) * XW;
            const float gA = QA.x - edge - EPSP;
            const float gB = QB.x - edge - EPSP;
            const float gA2 = (gA > 0.0f) ? gA * gA : 0.0f;
            const float gB2 = (gB > 0.0f) ? gB * gB : 0.0f;
            if (gA2 >= thA && gB2 >= thB) break;
            process_bin(l, gA2, gB2);
        }
        for (int r = h + 1; r < NBX; r++) {          // right expansion
            const float edge = XLO + r * XW;
            const float gA = edge - QA.x - EPSP;
            const float gB = edge - QB.x - EPSP;
            const float gA2 = (gA > 0.0f) ? gA * gA : 0.0f;
            const float gB2 = (gB > 0.0f) ? gB * gB : 0.0f;
            if (gA2 >= thA && gB2 >= thB) break;
            process_bin(r, gA2, gB2);
        }

        // ---- softmax per half-warp ----
        const int base = lane & 16;
        const float s_min = __shfl_sync(FULL, val, base);
        const float e = __expf(-(val - s_min) * inv_sigma);
        float esum = e;
        #pragma unroll
        for (int o = 8; o; o >>= 1) esum += __shfl_xor_sync(FULL, esum, o);
        const float w = e / esum;

        // ---- projected points ----
        const float4 gp = spts[idx];
        float wx = w * gp.x, wy = w * gp.y, wz = w * gp.z;
        #pragma unroll
        for (int o = 8; o; o >>= 1) {
            wx += __shfl_xor_sync(FULL, wx, o);
            wy += __shfl_xor_sync(FULL, wy, o);
            wz += __shfl_xor_sync(FULL, wz, o);
        }
        if (lane == 0) {
            out_pts[mA]         = wx;
            out_pts[M + mA]     = wy;
            out_pts[2 * M + mA] = wz;
        } else if (lane == 16) {
            out_pts[mB]         = wx;
            out_pts[M + mB]     = wy;
            out_pts[2 * M + mB] = wz;
        }

        // ---- features: stage (w, idx) in smem, broadcast-read ----
        const int og = __float_as_int(gp.w);
        mysw[lane] = w;
        mysi[lane] = og;
        __syncwarp();
        float a0 = 0.f, a1 = 0.f, c0 = 0.f, c1 = 0.f;
        #pragma unroll
        for (int j = 0; j < K; j++) {
            const float wj = mysw[j];
            const int   gj = mysi[j];
            const float2 f2 = *reinterpret_cast<const float2*>(
                featb + (size_t)gj * F + lane * 2);
            a0 = fmaf(wj, f2.x, a0);
            a1 = fmaf(wj, f2.y, a1);
        }
        #pragma unroll
        for (int j = 16; j < 16 + K; j++) {
            const float wj = mysw[j];
            const int   gj = mysi[j];
            const float2 f2 = *reinterpret_cast<const float2*>(
                featb + (size_t)gj * F + lane * 2);
            c0 = fmaf(wj, f2.x, c0);
            c1 = fmaf(wj, f2.y, c1);
        }
        __syncwarp();
        out_feat[(size_t)(2 * lane) * M + mA]     = a0;
        out_feat[(size_t)(2 * lane + 1) * M + mA] = a1;
        out_feat[(size_t)(2 * lane) * M + mB]     = c0;
        out_feat[(size_t)(2 * lane + 1) * M + mB] = c1;

        // ---- next task (static first round, then steal) ----
        if (lane == 0) pos = atomicAdd(&g_task[b], 1);
        pos = __shfl_sync(FULL, pos, 0);
    }
}

// ---------------------------------------------------------------------------
extern "C" void kernel_launch(void* const* d_in, const int* in_sizes, int n_in,
                              void* d_out, int out_size) {
    const float* pc   = (const float*)d_in[0];  // (B,3,N)
    const float* qc   = (const float*)d_in[1];  // (B,3,M)
    const float* pf   = (const float*)d_in[2];  // (B,F,N)
    const float* temp = (const float*)d_in[3];  // scalar
    float* out = (float*)d_out;                 // (B,3,M) ++ (B,F,M)
    (void)in_sizes; (void)n_in; (void)out_size;

    const int smem = 131072 + 16392 + 4096 + 4096;
    cudaFuncSetAttribute(soft_projection_query,
                         cudaFuncAttributeMaxDynamicSharedMemorySize, smem);

    // 8 binning blocks + 256 transpose blocks (8 tiles each) in one launch
    build_kernel<<<2 * B + 256, 1024>>>(pc, qc, pf);
    soft_projection_query<<<dim3(37, B), 1024, smem>>>(temp, out);
}

// round 13
// speedup vs baseline: 1.1138x; 1.1138x over previous
#include <cuda_runtime.h>
#include <cfloat>
#include <math.h>

#define FULL 0xffffffffu

constexpr int B = 4;
constexpr int N = 8192;
constexpr int M = 4096;
constexpr int F = 64;
constexpr int K = 16;
constexpr float MIN_SIGMA = 1e-4f;

constexpr int   NBX   = 128;      // x-bins
constexpr int   NYB   = 16;       // y-sub-bins per x-bin (width 0.4)
constexpr int   NBINS = NBX * NYB;
constexpr float XLO   = -3.2f;
constexpr float XW    = 0.05f;
constexpr float XINVW = 20.0f;
constexpr float YLO   = -3.2f;
constexpr float YINVW = 2.5f;
constexpr float EPSP  = 1e-4f;    // conservative pad (x gaps / y windows)
constexpr int   NWARPS = 37 * 32; // warps per batch

// Scratch (no allocations allowed)
__device__ float  g_featT[(size_t)B * N * F];    // (B,N,F) transposed features
__device__ float4 g_sorted[B * N];               // points, (xb,yb)-sorted
__device__ float4 g_qsorted[B * M];              // queries, (xb,yb)-sorted
__device__ int    g_start[B * (NBINS + 1)];      // point bin offsets
__device__ int    g_task[B];                     // dynamic task counters

// ---------------------------------------------------------------------------
__device__ __forceinline__ int xbinf(float x) {
    return min(NBX - 1, max(0, (int)floorf((x - XLO) * XINVW)));
}
__device__ __forceinline__ int ybinf(float y) {
    return min(NYB - 1, max(0, (int)floorf((y - YLO) * YINVW)));
}
__device__ __forceinline__ int bin2(float x, float y) {
    return xbinf(x) * NYB + ybinf(y);
}

// ---------------------------------------------------------------------------
// Fused build + transpose in ONE launch.
// Blocks 0..7: per-(kind,batch) binning (smem histogram + scan + scatter).
// Blocks 8..263: feature transpose, 8 32x32 tiles each.
// ---------------------------------------------------------------------------
__global__ void __launch_bounds__(1024, 1)
build_kernel(const float* __restrict__ pc, const float* __restrict__ qc,
             const float* __restrict__ feat) {
    __shared__ int cnt[NBINS];
    __shared__ int cur[NBINS];
    __shared__ int wsum[32];
    __shared__ float tile[32][33];
    const int g = blockIdx.x;
    const int tid = threadIdx.x;

    if (g >= 2 * B) {
        // ---- transpose role: 8 tiles of 32x32 ----
        const int tx = tid & 31, ty = tid >> 5;
        const int base_t = (g - 2 * B) * 8;
        #pragma unroll
        for (int it = 0; it < 8; it++) {
            const int tIdx = base_t + it;
            const int b   = tIdx >> 9;            // 512 tiles per batch
            const int rem = tIdx & 511;
            const int f0  = (rem >> 8) << 5;      // F/32 = 2
            const int n0  = (rem & 255) << 5;     // N/32 = 256
            __syncthreads();
            tile[ty][tx] = feat[((size_t)b * F + (f0 + ty)) * N + (n0 + tx)];
            __syncthreads();
            g_featT[((size_t)b * N + (n0 + ty)) * F + (f0 + tx)] = tile[tx][ty];
        }
        return;
    }

    // ---- binning role ----
    const bool isQ = g >= B;
    const int b = isQ ? g - B : g;
    const int n = isQ ? M : N;
    const float* src = isQ ? qc + (size_t)b * 3 * M : pc + (size_t)b * 3 * N;
    float4* dst = isQ ? g_qsorted + (size_t)b * M : g_sorted + (size_t)b * N;
    const int lane = tid & 31, wid = tid >> 5;

    if (g == 0 && tid < B) g_task[tid] = NWARPS;   // first NWARPS tasks static

    for (int i = tid; i < NBINS; i += 1024) cnt[i] = 0;
    __syncthreads();
    for (int i = tid; i < n; i += 1024)
        atomicAdd(&cnt[bin2(src[i], src[n + i])], 1);
    __syncthreads();

    // block exclusive scan, 2 bins per thread
    const int a0 = cnt[2 * tid], a1 = cnt[2 * tid + 1];
    const int s = a0 + a1;
    int inc = s;
    #pragma unroll
    for (int off = 1; off < 32; off <<= 1) {
        int nb = __shfl_up_sync(FULL, inc, off);
        if (lane >= off) inc += nb;
    }
    if (lane == 31) wsum[wid] = inc;
    __syncthreads();
    if (wid == 0) {
        int v = wsum[lane];
        #pragma unroll
        for (int off = 1; off < 32; off <<= 1) {
            int nb = __shfl_up_sync(FULL, v, off);
            if (lane >= off) v += nb;
        }
        wsum[lane] = v;
    }
    __syncthreads();
    const int excl = (wid ? wsum[wid - 1] : 0) + inc - s;
    cur[2 * tid] = excl;
    cur[2 * tid + 1] = excl + a0;
    if (!isQ) {
        g_start[b * (NBINS + 1) + 2 * tid]     = excl;
        g_start[b * (NBINS + 1) + 2 * tid + 1] = excl + a0;
        if (tid == 1023) g_start[b * (NBINS + 1) + NBINS] = excl + a0 + a1;
    }
    __syncthreads();
    for (int i = tid; i < n; i += 1024) {
        const float x = src[i], y = src[n + i], z = src[2 * n + i];
        const int pos = atomicAdd(&cur[bin2(x, y)], 1);
        dst[pos] = make_float4(x, y, z, __int_as_float(i));
    }
}

// ---------------------------------------------------------------------------
// Streamlined warp-cooperative top-K insert (non-improving candidates are
// natural no-ops). Caller refreshes the warp-uniform threshold per chunk.
// ---------------------------------------------------------------------------
__device__ __forceinline__ void topk_insert(float s, int pidx, int lane,
                                            float& val, int& idx,
                                            float threshold, int base) {
    unsigned bal = __ballot_sync(FULL, s < threshold);
    const bool mine = (unsigned)(lane - base) < (unsigned)K;
    while (bal) {
        const int src = __ffs(bal) - 1;
        bal &= bal - 1;
        const float cs = __shfl_sync(FULL, s, src);
        const int   ci = __shfl_sync(FULL, pidx, src);
        const unsigned less = __ballot_sync(FULL, mine && (val <= cs));
        const int pos = base + __popc(less);
        const float ot = __shfl_up_sync(FULL, val, 1);
        const int   oi = __shfl_up_sync(FULL, idx, 1);
        if (mine) {
            if (lane == pos)     { val = cs; idx = ci; }
            else if (lane > pos) { val = ot; idx = oi; }
        }
    }
}

// ---------------------------------------------------------------------------
// Query kernel: one warp, TWO (x,y)-adjacent queries per task.
// Seed: 32 points CENTERED on the pair's own sub-bin midpoint (two-sided
// in y). Each visited x-bin scanned as ONE contiguous y-window range.
// ---------------------------------------------------------------------------
__global__ void __launch_bounds__(1024, 1)
soft_projection_query(const float* __restrict__ temp,
                      float* __restrict__ out) {
    extern __shared__ char smraw[];
    float4* spts = (float4*)smraw;                                    // 128KB
    int*   cst = (int*)(smraw + 131072);                              // 2049 ints
    float* stw = (float*)(smraw + 131072 + 8200);                     // 4KB
    int*   sti = (int*)  (smraw + 131072 + 8200 + 4096);              // 4KB

    const int b = blockIdx.y;
    for (int i = threadIdx.x; i < N; i += blockDim.x) spts[i] = g_sorted[b * N + i];
    for (int i = threadIdx.x; i < NBINS + 1; i += blockDim.x)
        cst[i] = g_start[b * (NBINS + 1) + i];
    __syncthreads();

    const float t = *temp;
    const float inv_sigma = 1.0f / fmaxf(t * t, MIN_SIGMA);

    const int lane = threadIdx.x & 31;
    const int warp = threadIdx.x >> 5;
    float* mysw = stw + warp * 32;
    int*   mysi = sti + warp * 32;

    float* out_pts  = out + (size_t)b * 3 * M;
    float* out_feat = out + (size_t)B * 3 * M + (size_t)b * F * M;
    const float* featb = g_featT + (size_t)b * N * F;
    const float4* qs = g_qsorted + (size_t)b * M;

    constexpr int NT = M / 2;           // 2048 tasks per batch
    const int wg = blockIdx.x * 32 + warp;

    for (int pos = wg; pos < NT; ) {
        // center-out (x) order: longest tasks first
        const int task = (NT / 2) + ((pos & 1) ? -((pos + 1) >> 1) : (pos >> 1));

        const float4 QA = qs[2 * task];
        const float4 QB = qs[2 * task + 1];
        const int mA = __float_as_int(QA.w);
        const int mB = __float_as_int(QB.w);

        float val, thA, thB;
        int   idx;

        // ---- seed: 32 points centered on the pair's sub-bin midpoint ----
        const int h  = xbinf(0.5f * (QA.x + QB.x));
        const int yb = ybinf(0.5f * (QA.y + QB.y));
        const int c  = (cst[h * NYB + yb] + cst[h * NYB + yb + 1]) >> 1;
        const int s0 = min(max(c - 16, 0), N - 32);
        {
            const float4 pt = spts[s0 + lane];
            const float aX = pt.x - QA.x, aY = pt.y - QA.y, aZ = pt.z - QA.z;
            const float bX = pt.x - QB.x, bY = pt.y - QB.y, bZ = pt.z - QB.z;
            float dA = fmaf(aX, aX, fmaf(aY, aY, aZ * aZ));
            float dB = fmaf(bX, bX, fmaf(bY, bY, bZ * bZ));
            int pA = s0 + lane, pB = s0 + lane;
            #pragma unroll
            for (int k = 2; k <= 32; k <<= 1) {
                #pragma unroll
                for (int j = k >> 1; j > 0; j >>= 1) {
                    const float ovA = __shfl_xor_sync(FULL, dA, j);
                    const int   oiA = __shfl_xor_sync(FULL, pA, j);
                    const float ovB = __shfl_xor_sync(FULL, dB, j);
                    const int   oiB = __shfl_xor_sync(FULL, pB, j);
                    const bool ks = ((lane & j) == 0) == ((lane & k) == 0);
                    if (ks ? (ovA < dA) : (ovA > dA)) { dA = ovA; pA = oiA; }
                    if (ks ? (ovB < dB) : (ovB > dB)) { dB = ovB; pB = oiB; }
                }
            }
            const float dBs = __shfl_sync(FULL, dB, lane - 16);
            const int   pBs = __shfl_sync(FULL, pB, lane - 16);
            val = (lane < 16) ? dA : dBs;
            idx = (lane < 16) ? pA : pBs;
            thA = __shfl_sync(FULL, val, K - 1);
            thB = __shfl_sync(FULL, val, 16 + K - 1);
        }

        // ---- scan one contiguous range [s,e), 64-pt chunks, both queries ----
        auto scan_raw = [&](int s, int e) {
            for (int p0 = s; p0 < e; p0 += 64) {
                const int q0 = p0 + lane, q1 = p0 + lane + 32;
                float dA0 = FLT_MAX, dA1 = FLT_MAX, dB0 = FLT_MAX, dB1 = FLT_MAX;
                if (q0 < e) {
                    const float4 pt = spts[q0];
                    const float aX = pt.x - QA.x, aY = pt.y - QA.y, aZ = pt.z - QA.z;
                    const float bX = pt.x - QB.x, bY = pt.y - QB.y, bZ = pt.z - QB.z;
                    dA0 = fmaf(aX, aX, fmaf(aY, aY, aZ * aZ));
                    dB0 = fmaf(bX, bX, fmaf(bY, bY, bZ * bZ));
                }
                if (q1 < e) {
                    const float4 pt = spts[q1];
                    const float aX = pt.x - QA.x, aY = pt.y - QA.y, aZ = pt.z - QA.z;
                    const float bX = pt.x - QB.x, bY = pt.y - QB.y, bZ = pt.z - QB.z;
                    dA1 = fmaf(aX, aX, fmaf(aY, aY, aZ * aZ));
                    dB1 = fmaf(bX, bX, fmaf(bY, bY, bZ * bZ));
                }
                const bool cc = (fminf(dA0, dA1) < thA) | (fminf(dB0, dB1) < thB);
                if (__any_sync(FULL, cc)) {
                    topk_insert(dA0, q0, lane, val, idx, thA, 0);
                    topk_insert(dA1, q1, lane, val, idx, thA, 0);
                    topk_insert(dB0, q0, lane, val, idx, thB, 16);
                    topk_insert(dB1, q1, lane, val, idx, thB, 16);
                    thA = __shfl_sync(FULL, val, K - 1);
                    thB = __shfl_sync(FULL, val, 16 + K - 1);
                }
            }
        };
        // range minus the seed block [s0, s0+32)
        auto scan_range = [&](int s, int e) {
            scan_raw(s, min(e, s0));
            scan_raw(max(s, s0 + 32), e);
        };

        // one contiguous y-window scan of x-bin bx (gx^2 per query given)
        const float ymn = fminf(QA.y, QB.y), ymx = fmaxf(QA.y, QB.y);
        auto process_bin = [&](int bx, float gA2, float gB2) {
            const float avail = fmaxf(thA - gA2, thB - gB2);
            if (avail <= 0.0f) return;
            const float ry = sqrtf(avail) + EPSP;
            const int lo = max(0, min(NYB - 1, (int)floorf((ymn - ry - YLO) * YINVW)));
            const int hi = max(0, min(NYB - 1, (int)floorf((ymx + ry - YLO) * YINVW)));
            scan_range(cst[bx * NYB + lo], cst[bx * NYB + hi + 1]);
        };

        process_bin(h, 0.0f, 0.0f);                  // home x-bin
        for (int l = h - 1; l >= 0; l--) {           // left expansion
            const float edge = XLO + (l + 1) * XW;
            const float gA = QA.x - edge - EPSP;
            const float gB = QB.x - edge - EPSP;
            const float gA2 = (gA > 0.0f) ? gA * gA : 0.0f;
            const float gB2 = (gB > 0.0f) ? gB * gB : 0.0f;
            if (gA2 >= thA && gB2 >= thB) break;
            process_bin(l, gA2, gB2);
        }
        for (int r = h + 1; r < NBX; r++) {          // right expansion
            const float edge = XLO + r * XW;
            const float gA = edge - QA.x - EPSP;
            const float gB = edge - QB.x - EPSP;
            const float gA2 = (gA > 0.0f) ? gA * gA : 0.0f;
            const float gB2 = (gB > 0.0f) ? gB * gB : 0.0f;
            if (gA2 >= thA && gB2 >= thB) break;
            process_bin(r, gA2, gB2);
        }

        // ---- softmax per half-warp ----
        const int base = lane & 16;
        const float s_min = __shfl_sync(FULL, val, base);
        const float e = __expf(-(val - s_min) * inv_sigma);
        float esum = e;
        #pragma unroll
        for (int o = 8; o; o >>= 1) esum += __shfl_xor_sync(FULL, esum, o);
        const float w = e / esum;

        // ---- projected points ----
        const float4 gp = spts[idx];
        float wx = w * gp.x, wy = w * gp.y, wz = w * gp.z;
        #pragma unroll
        for (int o = 8; o; o >>= 1) {
            wx += __shfl_xor_sync(FULL, wx, o);
            wy += __shfl_xor_sync(FULL, wy, o);
            wz += __shfl_xor_sync(FULL, wz, o);
        }
        if (lane == 0) {
            out_pts[mA]         = wx;
            out_pts[M + mA]     = wy;
            out_pts[2 * M + mA] = wz;
        } else if (lane == 16) {
            out_pts[mB]         = wx;
            out_pts[M + mB]     = wy;
            out_pts[2 * M + mB] = wz;
        }

        // ---- features: stage (w, idx) in smem, broadcast-read ----
        const int og = __float_as_int(gp.w);
        mysw[lane] = w;
        mysi[lane] = og;
        __syncwarp();
        float a0 = 0.f, a1 = 0.f, c0 = 0.f, c1 = 0.f;
        #pragma unroll
        for (int j = 0; j < K; j++) {
            const float wj = mysw[j];
            const int   gj = mysi[j];
            const float2 f2 = *reinterpret_cast<const float2*>(
                featb + (size_t)gj * F + lane * 2);
            a0 = fmaf(wj, f2.x, a0);
            a1 = fmaf(wj, f2.y, a1);
        }
        #pragma unroll
        for (int j = 16; j < 16 + K; j++) {
            const float wj = mysw[j];
            const int   gj = mysi[j];
            const float2 f2 = *reinterpret_cast<const float2*>(
                featb + (size_t)gj * F + lane * 2);
            c0 = fmaf(wj, f2.x, c0);
            c1 = fmaf(wj, f2.y, c1);
        }
        __syncwarp();
        out_feat[(size_t)(2 * lane) * M + mA]     = a0;
        out_feat[(size_t)(2 * lane + 1) * M + mA] = a1;
        out_feat[(size_t)(2 * lane) * M + mB]     = c0;
        out_feat[(size_t)(2 * lane + 1) * M + mB] = c1;

        // ---- next task (static first round, then steal) ----
        if (lane == 0) pos = atomicAdd(&g_task[b], 1);
        pos = __shfl_sync(FULL, pos, 0);
    }
}

// ---------------------------------------------------------------------------
extern "C" void kernel_launch(void* const* d_in, const int* in_sizes, int n_in,
                              void* d_out, int out_size) {
    const float* pc   = (const float*)d_in[0];  // (B,3,N)
    const float* qc   = (const float*)d_in[1];  // (B,3,M)
    const float* pf   = (const float*)d_in[2];  // (B,F,N)
    const float* temp = (const float*)d_in[3];  // scalar
    float* out = (float*)d_out;                 // (B,3,M) ++ (B,F,M)
    (void)in_sizes; (void)n_in; (void)out_size;

    const int smem = 131072 + 8200 + 4096 + 4096;
    cudaFuncSetAttribute(soft_projection_query,
                         cudaFuncAttributeMaxDynamicSharedMemorySize, smem);

    // 8 binning blocks + 256 transpose blocks (8 tiles each) in one launch
    build_kernel<<<2 * B + 256, 1024>>>(pc, qc, pf);
    soft_projection_query<<<dim3(37, B), 1024, smem>>>(temp, out);
}